// round 10
// baseline (speedup 1.0000x reference)
#include <cuda_runtime.h>

#define BATCH 8
#define KPTS  65536
#define CH    128
#define NP    1024
#define BLKS_PER_B 16
#define THREADS_FPS 512
#define PTS_PER_THR 8
#define PAIRS 4
#define NW 16
#define NREC (BLKS_PER_B * NW)   /* 256 warp-records per batch */

// Flat per-warp exchange records, double-buffered by step parity.
// g_ra: {dist:32 | idx:16 (bits 15..30) | tag:15}; g_rc: {x,y,z,tag}.
// Both self-validate by tag; stale cross-replay contents are bit-identical
// (deterministic), so no init/reset is required.
__device__ unsigned long long g_ra[2][BATCH][NREC];
__device__ uint4              g_rc[2][BATCH][NREC];
__device__ int                g_inds[BATCH][NP];

// ---- packed f32x2 helpers (bit-identical to two scalar .rn ops) ----
__device__ __forceinline__ unsigned long long f2_pack(float lo, float hi) {
    unsigned long long r;
    asm("mov.b64 %0, {%1, %2};" : "=l"(r) : "f"(lo), "f"(hi));
    return r;
}
__device__ __forceinline__ void f2_unpack(unsigned long long v, float& lo, float& hi) {
    asm("mov.b64 {%0, %1}, %2;" : "=f"(lo), "=f"(hi) : "l"(v));
}
__device__ __forceinline__ unsigned long long f2_add(unsigned long long a, unsigned long long b) {
    unsigned long long r;
    asm("add.rn.f32x2 %0, %1, %2;" : "=l"(r) : "l"(a), "l"(b));
    return r;
}
__device__ __forceinline__ unsigned long long f2_mul(unsigned long long a, unsigned long long b) {
    unsigned long long r;
    asm("mul.rn.f32x2 %0, %1, %2;" : "=l"(r) : "l"(a), "l"(b));
    return r;
}

__device__ __forceinline__ void stg_q(uint4* p, unsigned x, unsigned y, unsigned z, unsigned w) {
    asm volatile("st.relaxed.gpu.global.v4.b32 [%0], {%1,%2,%3,%4};"
                 :: "l"(p), "r"(x), "r"(y), "r"(z), "r"(w) : "memory");
}
__device__ __forceinline__ void stg_u64(unsigned long long* p, unsigned long long v) {
    asm volatile("st.relaxed.gpu.global.b64 [%0], %1;"
                 :: "l"(p), "l"(v) : "memory");
}
__device__ __forceinline__ uint4 ldg_q(const uint4* p) {
    uint4 v;
    asm volatile("ld.relaxed.gpu.global.v4.b32 {%0,%1,%2,%3}, [%4];"
                 : "=r"(v.x), "=r"(v.y), "=r"(v.z), "=r"(v.w) : "l"(p) : "memory");
    return v;
}

__global__ void __launch_bounds__(THREADS_FPS, 1)
fps_kernel(const float* __restrict__ xyz,
           float* __restrict__ out_xyz,
           float* __restrict__ out_inds)
{
    const int tid  = threadIdx.x;
    const int b    = blockIdx.x / BLKS_PER_B;
    const int r    = blockIdx.x % BLKS_PER_B;
    const int lane = tid & 31;
    const int wid  = tid >> 5;

    __shared__ float s_px, s_py, s_pz;
    __shared__ uint4 s_log[NP];     // winner log (used by r==0 CTA only)

    const size_t bbase = (size_t)b * KPTS * 3;
    const int gp0 = r * (KPTS / BLKS_PER_B) + tid;  // pt idx = gp0 + i*512

    // Register-resident coords (two points per u64) + running min distance
    unsigned long long X[PAIRS], Y[PAIRS], Z[PAIRS];
    float dist[PTS_PER_THR];
#pragma unroll
    for (int j = 0; j < PAIRS; j++) {
        const float* p0 = xyz + bbase + (size_t)(gp0 + (2 * j) * THREADS_FPS) * 3;
        const float* p1 = xyz + bbase + (size_t)(gp0 + (2 * j + 1) * THREADS_FPS) * 3;
        X[j] = f2_pack(p0[0], p1[0]);
        Y[j] = f2_pack(p0[1], p1[1]);
        Z[j] = f2_pack(p0[2], p1[2]);
        dist[2 * j] = 1e10f;
        dist[2 * j + 1] = 1e10f;
    }

    float px = xyz[bbase + 0], py = xyz[bbase + 1], pz = xyz[bbase + 2];
    if (r == 0 && tid == 0)
        s_log[0] = make_uint4(0u, __float_as_uint(px), __float_as_uint(py),
                              __float_as_uint(pz));

    for (int t = 0; t < NP - 1; ++t) {
        const int par = t & 1;
        const unsigned tag = (unsigned)(t + 1);

        const unsigned long long nx2 = f2_pack(-px, -px);
        const unsigned long long ny2 = f2_pack(-py, -py);
        const unsigned long long nz2 = f2_pack(-pz, -pz);

        // ---- local distance update + argmax ----
        float bd = -1.0f;
        int bi = 0;
#pragma unroll
        for (int j = 0; j < PAIRS; j++) {
            unsigned long long dx = f2_add(X[j], nx2);
            unsigned long long dy = f2_add(Y[j], ny2);
            unsigned long long dz = f2_add(Z[j], nz2);
            unsigned long long dsq =
                f2_add(f2_add(f2_mul(dx, dx), f2_mul(dy, dy)), f2_mul(dz, dz));
            float d0, d1;  f2_unpack(dsq, d0, d1);
            float dd0 = fminf(dist[2 * j], d0);
            dist[2 * j] = dd0;
            if (dd0 > bd) { bd = dd0; bi = gp0 + (2 * j) * THREADS_FPS; }
            float dd1 = fminf(dist[2 * j + 1], d1);
            dist[2 * j + 1] = dd1;
            if (dd1 > bd) { bd = dd1; bi = gp0 + (2 * j + 1) * THREADS_FPS; }
        }

        // ---- warp argmax (max dist, lowest idx ties = jnp.argmax) ----
        unsigned db = __float_as_uint(bd);
        unsigned wm = __reduce_max_sync(0xFFFFFFFFu, db);
        unsigned cand = (db == wm) ? (unsigned)bi : 0x7FFFFFFFu;
        unsigned wi = __reduce_min_sync(0xFFFFFFFFu, cand);
        if (db == wm && (unsigned)bi == wi) {   // exactly one lane (idx unique)
            // extract this lane's winning coords from registers (i = 0..7)
            int i = (int)((wi - (unsigned)gp0) >> 9);
            int jlo = (i >> 1) & 1, jhi = (i >> 2) & 1, half = i & 1;
            unsigned long long xa = jlo ? X[1] : X[0], xb = jlo ? X[3] : X[2];
            unsigned long long ya = jlo ? Y[1] : Y[0], yb = jlo ? Y[3] : Y[2];
            unsigned long long za = jlo ? Z[1] : Z[0], zb = jlo ? Z[3] : Z[2];
            unsigned long long xs = jhi ? xb : xa;
            unsigned long long ys = jhi ? yb : ya;
            unsigned long long zs = jhi ? zb : za;
            float x0, x1, y0, y1, z0, z1;
            f2_unpack(xs, x0, x1); f2_unpack(ys, y0, y1); f2_unpack(zs, z0, z1);
            float wx = half ? x1 : x0, wy = half ? y1 : y0, wz = half ? z1 : z0;

            // flat publish: warp record straight to L2 (no intra-CTA reduce)
            int pos = r * NW + wid;
            stg_q(&g_rc[par][b][pos],
                  __float_as_uint(wx), __float_as_uint(wy), __float_as_uint(wz), tag);
            stg_u64(&g_ra[par][b][pos],
                    ((unsigned long long)wm << 32) |
                    ((unsigned long long)wi << 15) | (unsigned long long)tag);
        }

        if (wid == 0) {
            // ---- poll all 256 records (12 pipelined LDG.128 per lane) ----
            const uint4* pa = (const uint4*)g_ra[par][b];  // 128 quads = 256 u64
            const uint4* pc = g_rc[par][b];                // 256 quads
            uint4 va[4], vc[8];
            bool done;
            do {
#pragma unroll
                for (int k = 0; k < 4; k++) va[k] = ldg_q(pa + k * 32 + lane);
#pragma unroll
                for (int k = 0; k < 8; k++) vc[k] = ldg_q(pc + k * 32 + lane);
                done = true;
#pragma unroll
                for (int k = 0; k < 4; k++)
                    done = done && ((va[k].x & 0x7FFFu) == tag)
                                && ((va[k].z & 0x7FFFu) == tag);
#pragma unroll
                for (int k = 0; k < 8; k++)
                    done = done && (vc[k].w == tag);
            } while (!__all_sync(0xFFFFFFFFu, done));

            // ---- lane-local reduce over 8 records ----
            unsigned bd2 = 0u, bi2 = 0x7FFFFFFFu;
#pragma unroll
            for (int k = 0; k < 4; k++) {
                unsigned dA = va[k].y, iA = (va[k].x >> 15) & 0xFFFFu;
                if (dA > bd2 || (dA == bd2 && iA < bi2)) { bd2 = dA; bi2 = iA; }
                unsigned dB = va[k].w, iB = (va[k].z >> 15) & 0xFFFFu;
                if (dB > bd2 || (dB == bd2 && iB < bi2)) { bd2 = dB; bi2 = iB; }
            }
            // ---- warp reduce over 32 lanes ----
            unsigned gm = __reduce_max_sync(0xFFFFFFFFu, bd2);
            unsigned c3 = (bd2 == gm) ? bi2 : 0x7FFFFFFFu;
            unsigned gi = __reduce_min_sync(0xFFFFFFFFu, c3);

            // winner coords from polled quads: record pos -> (lane, slot)
            int pos = (int)(((gi >> 12) << 4) | ((gi >> 5) & 15));
            int owner = pos & 31, slot = pos >> 5;
            uint4 s = vc[0];
#pragma unroll
            for (int k = 1; k < 8; k++) s = (slot == k) ? vc[k] : s;
            unsigned ux = __shfl_sync(0xFFFFFFFFu, s.x, owner);
            unsigned uy = __shfl_sync(0xFFFFFFFFu, s.y, owner);
            unsigned uz = __shfl_sync(0xFFFFFFFFu, s.z, owner);

            if (lane == 0) {
                s_px = __uint_as_float(ux);
                s_py = __uint_as_float(uy);
                s_pz = __uint_as_float(uz);
                if (r == 0) s_log[t + 1] = make_uint4(gi, ux, uy, uz);
            }
        }
        __syncthreads();            // single bar per step: bcast visibility
        px = s_px; py = s_py; pz = s_pz;
    }

    // ---- flush winner log (leader CTA of each batch) ----
    if (r == 0) {
        for (int j = tid; j < NP; j += THREADS_FPS) {
            uint4 e = s_log[j];
            g_inds[b][j] = (int)e.x;
            out_inds[b * NP + j] = (float)e.x;
            float* o = out_xyz + ((size_t)b * NP + j) * 3;
            o[0] = __uint_as_float(e.y);
            o[1] = __uint_as_float(e.z);
            o[2] = __uint_as_float(e.w);
        }
    }
}

// new_features[b][c][j] = features[b][c][inds[b][j]]
__global__ void gather_feat_kernel(const float* __restrict__ feat,
                                   float* __restrict__ out_feat)
{
    int t = blockIdx.x * blockDim.x + threadIdx.x;
    int j = t & (NP - 1);
    int c = (t >> 10) & (CH - 1);
    int b = t >> 17;
    int ind = g_inds[b][j];
    out_feat[t] = feat[(((size_t)b * CH + c) << 16) + ind];
}

extern "C" void kernel_launch(void* const* d_in, const int* in_sizes, int n_in,
                              void* d_out, int out_size)
{
    const float* xyz  = (const float*)d_in[0]; // (B,K,3)
    const float* feat = (const float*)d_in[1]; // (B,C,K)
    float* out = (float*)d_out;

    float* out_xyz  = out;                                  // B*NP*3
    float* out_feat = out + (size_t)BATCH * NP * 3;         // B*C*NP
    float* out_inds = out_feat + (size_t)BATCH * CH * NP;   // B*NP

    fps_kernel<<<BATCH * BLKS_PER_B, THREADS_FPS>>>(xyz, out_xyz, out_inds);

    int total = BATCH * CH * NP;
    gather_feat_kernel<<<total / 256, 256>>>(feat, out_feat);
}

// round 12
// speedup vs baseline: 1.2700x; 1.2700x over previous
#include <cuda_runtime.h>

#define BATCH 8
#define KPTS  65536
#define CH    128
#define NP    1024
#define BLKS_PER_B 16
#define THREADS_FPS 512
#define PTS_PER_THR 8
#define PAIRS 4
#define NW 16
#define EXW 15   /* exchange warp (highest wid = highest arbiter priority) */

// R8-proven exchange transport: per CTA one 128B slot (2 quads):
// quad0 = {dist, idx, 0, tag}, quad1 = {x, y, z, tag}; parity double-buffered,
// tag = t+1 validates. Stale cross-replay contents are bit-identical
// (deterministic), so no init/reset is needed.
__device__ uint4 g_slot[2][BATCH][BLKS_PER_B][8];
__device__ int   g_inds[BATCH][NP];

// ---- packed f32x2 helpers (bit-identical to two scalar .rn ops) ----
__device__ __forceinline__ unsigned long long f2_pack(float lo, float hi) {
    unsigned long long r;
    asm("mov.b64 %0, {%1, %2};" : "=l"(r) : "f"(lo), "f"(hi));
    return r;
}
__device__ __forceinline__ void f2_unpack(unsigned long long v, float& lo, float& hi) {
    asm("mov.b64 {%0, %1}, %2;" : "=f"(lo), "=f"(hi) : "l"(v));
}
__device__ __forceinline__ unsigned long long f2_add(unsigned long long a, unsigned long long b) {
    unsigned long long r;
    asm("add.rn.f32x2 %0, %1, %2;" : "=l"(r) : "l"(a), "l"(b));
    return r;
}
__device__ __forceinline__ unsigned long long f2_mul(unsigned long long a, unsigned long long b) {
    unsigned long long r;
    asm("mul.rn.f32x2 %0, %1, %2;" : "=l"(r) : "l"(a), "l"(b));
    return r;
}

__device__ __forceinline__ void stg_q(uint4* p, unsigned x, unsigned y, unsigned z, unsigned w) {
    asm volatile("st.relaxed.gpu.global.v4.b32 [%0], {%1,%2,%3,%4};"
                 :: "l"(p), "r"(x), "r"(y), "r"(z), "r"(w) : "memory");
}
__device__ __forceinline__ uint4 ldg_q(const uint4* p) {
    uint4 v;
    asm volatile("ld.relaxed.gpu.global.v4.b32 {%0,%1,%2,%3}, [%4];"
                 : "=r"(v.x), "=r"(v.y), "=r"(v.z), "=r"(v.w) : "l"(p) : "memory");
    return v;
}

struct Win { unsigned gi, ux, uy, uz; };

// Poll the 16 CTA records of one batch (R8 logic verbatim).
__device__ __forceinline__ Win poll16(const uint4* base, unsigned tag, int lane) {
    const uint4* gp = base + (lane & 15) * 8 + (lane >> 4);
    uint4 g;
    do { g = ldg_q(gp); } while (g.w != tag);
    unsigned d3 = (lane < 16) ? g.x : 0u;
    unsigned i3 = (lane < 16) ? g.y : 0x7FFFFFFFu;
    unsigned gm = __reduce_max_sync(0xFFFFFFFFu, d3);
    unsigned c3 = (d3 == gm && lane < 16) ? i3 : 0x7FFFFFFFu;
    unsigned gi = __reduce_min_sync(0xFFFFFFFFu, c3);
    unsigned bal = __ballot_sync(0xFFFFFFFFu, lane < 16 && d3 == gm && i3 == gi);
    int gs = (__ffs(bal) - 1) + 16;     // lane holding winner coords
    Win w;
    w.gi = gi;
    w.ux = __shfl_sync(0xFFFFFFFFu, g.x, gs);
    w.uy = __shfl_sync(0xFFFFFFFFu, g.y, gs);
    w.uz = __shfl_sync(0xFFFFFFFFu, g.z, gs);
    return w;
}

// CTA-level argmax over 16 warp records, publish to this CTA's slot.
__device__ __forceinline__ void reduce_publish(const uint4* s_wa, const uint4* s_wc,
                                               uint4* slot, unsigned tag, int lane) {
    uint4 q = (lane < NW) ? s_wa[lane] : s_wc[lane - NW];
    unsigned d2 = (lane < NW) ? q.x : 0u;
    unsigned i2 = (lane < NW) ? q.y : 0x7FFFFFFFu;
    unsigned wm2 = __reduce_max_sync(0xFFFFFFFFu, d2);
    unsigned c2  = (d2 == wm2 && lane < NW) ? i2 : 0x7FFFFFFFu;
    unsigned wi2 = __reduce_min_sync(0xFFFFFFFFu, c2);
    unsigned bal = __ballot_sync(0xFFFFFFFFu, lane < NW && d2 == wm2 && i2 == wi2);
    int ws = __ffs(bal) - 1;
    if (lane == ws)      stg_q(slot + 0, wm2, wi2, 0u, tag);
    if (lane == ws + NW) stg_q(slot + 1, q.x, q.y, q.z, tag);
}

// One FPS distance-update step for 8 register-resident points; warp argmax;
// winner lane extracts its coords and stores both warp records to smem.
__device__ __forceinline__ void step_compute(
    const unsigned long long (&X)[PAIRS], const unsigned long long (&Y)[PAIRS],
    const unsigned long long (&Z)[PAIRS], float (&dist)[PTS_PER_THR],
    float px, float py, float pz, int gp0,
    uint4* s_wa, uint4* s_wc, int lane, int wid)
{
    const unsigned long long nx2 = f2_pack(-px, -px);
    const unsigned long long ny2 = f2_pack(-py, -py);
    const unsigned long long nz2 = f2_pack(-pz, -pz);

    float bd = -1.0f;
    int bi = 0;
#pragma unroll
    for (int j = 0; j < PAIRS; j++) {
        unsigned long long dx = f2_add(X[j], nx2);
        unsigned long long dy = f2_add(Y[j], ny2);
        unsigned long long dz = f2_add(Z[j], nz2);
        unsigned long long dsq =
            f2_add(f2_add(f2_mul(dx, dx), f2_mul(dy, dy)), f2_mul(dz, dz));
        float d0, d1;  f2_unpack(dsq, d0, d1);
        float dd0 = fminf(dist[2 * j], d0);
        dist[2 * j] = dd0;
        if (dd0 > bd) { bd = dd0; bi = gp0 + (2 * j) * THREADS_FPS; }
        float dd1 = fminf(dist[2 * j + 1], d1);
        dist[2 * j + 1] = dd1;
        if (dd1 > bd) { bd = dd1; bi = gp0 + (2 * j + 1) * THREADS_FPS; }
    }

    unsigned db = __float_as_uint(bd);
    unsigned wm = __reduce_max_sync(0xFFFFFFFFu, db);
    unsigned cand = (db == wm) ? (unsigned)bi : 0x7FFFFFFFu;
    unsigned wi = __reduce_min_sync(0xFFFFFFFFu, cand);
    if (db == wm && (unsigned)bi == wi) {   // exactly one lane (idx unique)
        int i = (int)((wi - (unsigned)gp0) >> 9);
        int jlo = (i >> 1) & 1, jhi = (i >> 2) & 1, half = i & 1;
        unsigned long long xa = jlo ? X[1] : X[0], xb = jlo ? X[3] : X[2];
        unsigned long long ya = jlo ? Y[1] : Y[0], yb = jlo ? Y[3] : Y[2];
        unsigned long long za = jlo ? Z[1] : Z[0], zb = jlo ? Z[3] : Z[2];
        unsigned long long xs = jhi ? xb : xa;
        unsigned long long ys = jhi ? yb : ya;
        unsigned long long zs = jhi ? zb : za;
        float x0, x1, y0, y1, z0, z1;
        f2_unpack(xs, x0, x1); f2_unpack(ys, y0, y1); f2_unpack(zs, z0, z1);
        float wx = half ? x1 : x0, wy = half ? y1 : y0, wz = half ? z1 : z0;
        s_wa[wid] = make_uint4(wm, wi, 0u, 0u);
        s_wc[wid] = make_uint4(__float_as_uint(wx), __float_as_uint(wy),
                               __float_as_uint(wz), 0u);
    }
}

__global__ void __launch_bounds__(THREADS_FPS, 1)
fps_kernel(const float* __restrict__ xyz,
           float* __restrict__ out_xyz,
           float* __restrict__ out_inds)
{
    const int tid  = threadIdx.x;
    const int grp  = blockIdx.x / BLKS_PER_B;   // batch pair 0..3
    const int r    = blockIdx.x % BLKS_PER_B;
    const int lane = tid & 31;
    const int wid  = tid >> 5;
    const int bA = 2 * grp, bB = 2 * grp + 1;

    __shared__ uint4 s_wa[2][NW], s_wc[2][NW];   // per-batch warp records
    __shared__ float s_bc[2][3];                 // per-batch winner coords
    __shared__ uint4 s_log[2][NP];               // winner logs (r==0 only)

    const size_t baseA = (size_t)bA * KPTS * 3;
    const size_t baseB = (size_t)bB * KPTS * 3;
    const int gp0 = r * (KPTS / BLKS_PER_B) + tid;  // pt idx = gp0 + i*512

    unsigned long long XA[PAIRS], YA[PAIRS], ZA[PAIRS];
    unsigned long long XB[PAIRS], YB[PAIRS], ZB[PAIRS];
    float dA[PTS_PER_THR], dB[PTS_PER_THR];
#pragma unroll
    for (int j = 0; j < PAIRS; j++) {
        const float* a0 = xyz + baseA + (size_t)(gp0 + (2 * j) * THREADS_FPS) * 3;
        const float* a1 = xyz + baseA + (size_t)(gp0 + (2 * j + 1) * THREADS_FPS) * 3;
        XA[j] = f2_pack(a0[0], a1[0]);
        YA[j] = f2_pack(a0[1], a1[1]);
        ZA[j] = f2_pack(a0[2], a1[2]);
        const float* b0 = xyz + baseB + (size_t)(gp0 + (2 * j) * THREADS_FPS) * 3;
        const float* b1 = xyz + baseB + (size_t)(gp0 + (2 * j + 1) * THREADS_FPS) * 3;
        XB[j] = f2_pack(b0[0], b1[0]);
        YB[j] = f2_pack(b0[1], b1[1]);
        ZB[j] = f2_pack(b0[2], b1[2]);
        dA[2 * j] = 1e10f; dA[2 * j + 1] = 1e10f;
        dB[2 * j] = 1e10f; dB[2 * j + 1] = 1e10f;
    }

    float pxA = xyz[baseA + 0], pyA = xyz[baseA + 1], pzA = xyz[baseA + 2];
    float pxB = xyz[baseB + 0], pyB = xyz[baseB + 1], pzB = xyz[baseB + 2];
    if (tid == 0) {
        s_bc[1][0] = pxB; s_bc[1][1] = pyB; s_bc[1][2] = pzB;
        if (r == 0) {
            s_log[0][0] = make_uint4(0u, __float_as_uint(pxA),
                                     __float_as_uint(pyA), __float_as_uint(pzA));
            s_log[1][0] = make_uint4(0u, __float_as_uint(pxB),
                                     __float_as_uint(pyB), __float_as_uint(pzB));
        }
    }
    __syncthreads();

    for (int t = 0; t < NP - 1; ++t) {
        const int par = t & 1;
        const unsigned tag = (unsigned)(t + 1);

        // ---- phase A: finalize B(t-1), compute A(t) ----
        if (wid == EXW && t > 0) {
            Win w = poll16(&g_slot[(t - 1) & 1][bB][0][0], (unsigned)t, lane);
            if (lane == 0) {
                s_bc[1][0] = __uint_as_float(w.ux);
                s_bc[1][1] = __uint_as_float(w.uy);
                s_bc[1][2] = __uint_as_float(w.uz);
                if (r == 0) s_log[1][t] = make_uint4(w.gi, w.ux, w.uy, w.uz);
            }
        }
        step_compute(XA, YA, ZA, dA, pxA, pyA, pzA, gp0,
                     s_wa[0], s_wc[0], lane, wid);
        __syncthreads();   // bar1: s_wa[0] complete, s_bc[1] visible

        // ---- phase 1: publish A(t), compute B(t) ----
        if (wid == EXW)
            reduce_publish(s_wa[0], s_wc[0], &g_slot[par][bA][r][0], tag, lane);
        pxB = s_bc[1][0]; pyB = s_bc[1][1]; pzB = s_bc[1][2];
        step_compute(XB, YB, ZB, dB, pxB, pyB, pzB, gp0,
                     s_wa[1], s_wc[1], lane, wid);
        __syncthreads();   // bar2: s_wa[1] complete

        // ---- phase 2: publish B(t), finalize A(t) ----
        if (wid == EXW) {
            reduce_publish(s_wa[1], s_wc[1], &g_slot[par][bB][r][0], tag, lane);
            Win w = poll16(&g_slot[par][bA][0][0], tag, lane);
            if (lane == 0) {
                s_bc[0][0] = __uint_as_float(w.ux);
                s_bc[0][1] = __uint_as_float(w.uy);
                s_bc[0][2] = __uint_as_float(w.uz);
                if (r == 0) s_log[0][t + 1] = make_uint4(w.gi, w.ux, w.uy, w.uz);
            }
        }
        __syncthreads();   // bar3: s_bc[0] visible
        pxA = s_bc[0][0]; pyA = s_bc[0][1]; pzA = s_bc[0][2];
    }

    // final B winner (tag NP-1) -> log (only the logging CTA needs it)
    if (r == 0 && wid == EXW) {
        Win w = poll16(&g_slot[(NP - 2) & 1][bB][0][0], (unsigned)(NP - 1), lane);
        if (lane == 0) s_log[1][NP - 1] = make_uint4(w.gi, w.ux, w.uy, w.uz);
    }
    __syncthreads();

    // ---- flush winner logs for both batches (r==0 CTA of each group) ----
    if (r == 0) {
        for (int j = tid; j < NP; j += THREADS_FPS) {
            uint4 eA = s_log[0][j];
            g_inds[bA][j] = (int)eA.x;
            out_inds[bA * NP + j] = (float)eA.x;
            float* oA = out_xyz + ((size_t)bA * NP + j) * 3;
            oA[0] = __uint_as_float(eA.y);
            oA[1] = __uint_as_float(eA.z);
            oA[2] = __uint_as_float(eA.w);

            uint4 eB = s_log[1][j];
            g_inds[bB][j] = (int)eB.x;
            out_inds[bB * NP + j] = (float)eB.x;
            float* oB = out_xyz + ((size_t)bB * NP + j) * 3;
            oB[0] = __uint_as_float(eB.y);
            oB[1] = __uint_as_float(eB.z);
            oB[2] = __uint_as_float(eB.w);
        }
    }
}

// new_features[b][c][j] = features[b][c][inds[b][j]]
__global__ void gather_feat_kernel(const float* __restrict__ feat,
                                   float* __restrict__ out_feat)
{
    int t = blockIdx.x * blockDim.x + threadIdx.x;
    int j = t & (NP - 1);
    int c = (t >> 10) & (CH - 1);
    int b = t >> 17;
    int ind = g_inds[b][j];
    out_feat[t] = feat[(((size_t)b * CH + c) << 16) + ind];
}

extern "C" void kernel_launch(void* const* d_in, const int* in_sizes, int n_in,
                              void* d_out, int out_size)
{
    const float* xyz  = (const float*)d_in[0]; // (B,K,3)
    const float* feat = (const float*)d_in[1]; // (B,C,K)
    float* out = (float*)d_out;

    float* out_xyz  = out;                                  // B*NP*3
    float* out_feat = out + (size_t)BATCH * NP * 3;         // B*C*NP
    float* out_inds = out_feat + (size_t)BATCH * CH * NP;   // B*NP

    // 64 CTAs: 4 batch-pairs x 16 CTAs, two interleaved batches per CTA
    fps_kernel<<<(BATCH / 2) * BLKS_PER_B, THREADS_FPS>>>(xyz, out_xyz, out_inds);

    int total = BATCH * CH * NP;
    gather_feat_kernel<<<total / 256, 256>>>(feat, out_feat);
}